// round 16
// baseline (speedup 1.0000x reference)
#include <cuda_runtime.h>
#include <cuda_fp16.h>
#include <math.h>

// Problem dims
#define T_STEPS 2048
#define BATCH   64
#define DIN     512
#define HDIM    512
#define G4      2048            // 4*H
#define M_ROWS  131072          // T*B
#define NBLK    32              // lstm CTAs (was 128)

typedef unsigned long long u64;
typedef unsigned int u32;

// Scratch (device globals: allocation-free contract)
// g_xproj layout: [t][cta(32)][batch(64)][q(16)][g(4)] fp32
__device__ float g_xproj[268435456];            // 1 GiB
__device__ __half g_xh[67108864];               // X fp16
__device__ __half g_wxt[1048576];               // Wx^T fp16 [2048][512]
__device__ __half g_hf[2][32768];               // h state fp16 [buf][b*512+col]
__device__ unsigned long long g_arrive  = 0ULL;
__device__ unsigned long long g_release = 0ULL;

// ---------------------------------------------------------------------------
// PTX helpers
// ---------------------------------------------------------------------------
__device__ __forceinline__ u32 smem_u32(const void* p) {
    u32 a;
    asm("{ .reg .u64 t; cvta.to.shared.u64 t, %1; cvt.u32.u64 %0, t; }"
        : "=r"(a) : "l"(p));
    return a;
}
__device__ __forceinline__ void cpa16(u32 dst, const void* src) {
    asm volatile("cp.async.cg.shared.global [%0], [%1], 16;"
                 :: "r"(dst), "l"(src));
}
#define CP_COMMIT() asm volatile("cp.async.commit_group;" ::: "memory")

#define LDSM4(r0, r1, r2, r3, a) \
    asm volatile("ldmatrix.sync.aligned.m8n8.x4.shared.b16 {%0,%1,%2,%3}, [%4];" \
                 : "=r"(r0), "=r"(r1), "=r"(r2), "=r"(r3) : "r"(a))

#define MMA_F16B(c, a, b) \
    asm volatile("mma.sync.aligned.m16n8k16.row.col.f32.f16.f16.f32 " \
                 "{%0,%1,%2,%3}, {%4,%5,%6,%7}, {%8,%9}, {%0,%1,%2,%3};" \
                 : "+f"((c)[0]), "+f"((c)[1]), "+f"((c)[2]), "+f"((c)[3]) \
                 : "r"((a)[0]), "r"((a)[1]), "r"((a)[2]), "r"((a)[3]), \
                   "r"((b)[0]), "r"((b)[1]))

#define MMA_F16(c, a, b0r, b1r) \
    asm volatile("mma.sync.aligned.m16n8k16.row.col.f32.f16.f16.f32 " \
                 "{%0,%1,%2,%3}, {%4,%5,%6,%7}, {%8,%9}, {%0,%1,%2,%3};" \
                 : "+f"((c)[0]), "+f"((c)[1]), "+f"((c)[2]), "+f"((c)[3]) \
                 : "r"((a)[0]), "r"((a)[1]), "r"((a)[2]), "r"((a)[3]), \
                   "r"(b0r), "r"(b1r))

#define BAR_SYNC(id, cnt) \
    asm volatile("bar.sync %0, %1;" :: "r"(id), "r"(cnt) : "memory")

// ---------------------------------------------------------------------------
// Conversion kernels: fp32 -> fp16
// ---------------------------------------------------------------------------
__global__ __launch_bounds__(256) void convert_x(const float* __restrict__ X) {
    size_t i = (size_t)blockIdx.x * 256 + threadIdx.x;
    float4 v = ((const float4*)X)[i];
    __half2* ph = (__half2*)g_xh;
    ph[i * 2]     = __floats2half2_rn(v.x, v.y);
    ph[i * 2 + 1] = __floats2half2_rn(v.z, v.w);
}

__global__ __launch_bounds__(256) void convert_w(const float* __restrict__ Wx) {
    int idx = blockIdx.x * 256 + threadIdx.x;
    int k = idx >> 11, g = idx & 2047;
    g_wxt[(size_t)g * 512 + k] = __float2half_rn(Wx[idx]);
}

// ---------------------------------------------------------------------------
// Kernel 1: x_proj = X @ Wx + bx via mma.sync fp16 (K=512), 3-stage pipeline.
// Epilogue writes the PERMUTED layout [t][cta32][b][q16][g4].
// ---------------------------------------------------------------------------
#define TILE_B   10240
#define GSTAGE   20480
#define GSM_TOTAL (3 * GSTAGE)

__device__ __forceinline__ void load_tile(
    u32 sA, u32 sB,
    const __half* __restrict__ asrc,
    const __half* __restrict__ bsrc,
    int kc, int tid)
{
#pragma unroll
    for (int p = 0; p < 2; p++) {
        int idx = tid + p * 256;
        int row = idx >> 2, seg = idx & 3;
        cpa16(sA + row * 80 + seg * 16,
              (const char*)(asrc + (size_t)row * 512 + kc) + seg * 16);
    }
#pragma unroll
    for (int p = 0; p < 2; p++) {
        int idx = tid + p * 256;
        int row = idx >> 2, seg = idx & 3;
        cpa16(sB + row * 80 + seg * 16,
              (const char*)(bsrc + (size_t)row * 512 + kc) + seg * 16);
    }
}

__global__ __launch_bounds__(256, 2) void gemm_xproj_hmma(
    const float* __restrict__ bias)
{
    extern __shared__ char gsm[];
    u32 sb = smem_u32(gsm);

    const int tid  = threadIdx.x;
    const int lane = tid & 31;
    const int wid  = tid >> 5;
    const int m0w  = (wid & 3) * 32;
    const int n0w  = (wid >> 2) * 64;

    const int bn = blockIdx.x * 128;
    const int m0 = blockIdx.y * 128;

    const __half* a_src = g_xh + (size_t)m0 * 512;
    const __half* b_src = g_wxt + (size_t)bn * 512;

    float acc[2][8][4];
#pragma unroll
    for (int mt = 0; mt < 2; mt++)
#pragma unroll
        for (int nt = 0; nt < 8; nt++)
#pragma unroll
            for (int r = 0; r < 4; r++) acc[mt][nt][r] = 0.f;

    load_tile(sb,          sb + TILE_B,          a_src, b_src, 0,  tid);
    CP_COMMIT();
    load_tile(sb + GSTAGE, sb + GSTAGE + TILE_B, a_src, b_src, 32, tid);
    CP_COMMIT();

    int st = 0, pst = 2;
#pragma unroll 1
    for (int c = 0; c < 16; c++) {
        if (c < 15) {
            asm volatile("cp.async.wait_group 1;" ::: "memory");
        } else {
            asm volatile("cp.async.wait_group 0;" ::: "memory");
        }
        __syncthreads();

        if (c + 2 < 16) {
            const int kc = (c + 2) * 32;
            u32 base = sb + (u32)pst * GSTAGE;
            load_tile(base, base + TILE_B, a_src, b_src, kc, tid);
            CP_COMMIT();
        }

        const u32 sA = sb + (u32)st * GSTAGE;
        const u32 sB = sA + TILE_B;

#pragma unroll
        for (int k16 = 0; k16 < 2; k16++) {
            const int kb = k16 * 16;
            u32 a_frag[2][4];
#pragma unroll
            for (int mt = 0; mt < 2; mt++) {
                u32 addr = sA + (u32)((m0w + mt * 16 + (lane & 15)) * 40
                                      + kb + (lane >> 4) * 8) * 2;
                LDSM4(a_frag[mt][0], a_frag[mt][1], a_frag[mt][2], a_frag[mt][3], addr);
            }
            u32 b_frag[8][2];
#pragma unroll
            for (int ntp = 0; ntp < 4; ntp++) {
                u32 addr = sB + (u32)((n0w + ntp * 16 + (lane & 15)) * 40
                                      + kb + (lane >> 4) * 8) * 2;
                u32 r0, r1, r2, r3;
                LDSM4(r0, r1, r2, r3, addr);
                b_frag[2 * ntp][0]     = r0;
                b_frag[2 * ntp][1]     = r2;
                b_frag[2 * ntp + 1][0] = r1;
                b_frag[2 * ntp + 1][1] = r3;
            }
#pragma unroll
            for (int mt = 0; mt < 2; mt++)
#pragma unroll
                for (int nt = 0; nt < 8; nt++)
                    MMA_F16B(acc[mt][nt], a_frag[mt], b_frag[nt]);
        }

        st = (st == 2) ? 0 : st + 1;
        pst = (pst == 2) ? 0 : pst + 1;
    }

    // Epilogue: bias + permuted store [t][cta32][b][q16][g4]
    const int mrow  = m0 + m0w + (lane >> 2);
    const int ncol0 = bn + n0w + (lane & 3) * 2;
#pragma unroll
    for (int mt = 0; mt < 2; mt++) {
#pragma unroll
        for (int nt = 0; nt < 8; nt++) {
            const int col = ncol0 + nt * 8;       // even
            const float2 bs = __ldg((const float2*)(bias + col));
            const int g = col >> 9;
            const int hcol = col & 511;
            const size_t cb = (size_t)(hcol >> 4) * 4096 + (hcol & 15) * 4 + g;
            const int rA = mrow + mt * 16;
            const int rB = rA + 8;
            const size_t baseA = (size_t)(rA >> 6) * 131072 + (rA & 63) * 64;
            const size_t baseB = (size_t)(rB >> 6) * 131072 + (rB & 63) * 64;
            g_xproj[baseA + cb]     = acc[mt][nt][0] + bs.x;
            g_xproj[baseA + cb + 4] = acc[mt][nt][1] + bs.y;
            g_xproj[baseB + cb]     = acc[mt][nt][2] + bs.x;
            g_xproj[baseB + cb + 4] = acc[mt][nt][3] + bs.y;
        }
    }
}

// ---------------------------------------------------------------------------
// Kernel 2: persistent recurrence, 32 CTAs x 512 threads (16 warps).
// Warp (grp, mw, nh): m32 (batches mw*32..+32) x n16 (gate-cols nh*16..+16)
// x k-half (grp). Wh fp16 in registers. Producer warps each broadcast 4KB;
// consumers gated by a 128-thread named barrier per (grp,mw) group.
// ---------------------------------------------------------------------------
#define APB 1040          // h row pitch bytes (512 fp16 + 8 pad)
#define SM_A    0         // 64*1040 = 66560
#define SM_RED  66560     // 16384: [grp2][sub8][lane32][mt2] float4
#define SM_WST  82944     // W plane: 64*1040 = 66560
#define SM_TOTAL 149504

__device__ __forceinline__ void grid_barrier() {
    __syncthreads();
    if (threadIdx.x == 0) {
        __threadfence();
        unsigned long long t = atomicAdd(&g_arrive, 1ULL) + 1ULL;
        unsigned long long n = (unsigned long long)NBLK;
        unsigned long long target = ((t + n - 1ULL) / n) * n;
        if (t == target) {
            atomicMax(&g_release, target);
        } else {
            unsigned long long r;
            do {
                asm volatile("ld.volatile.global.u64 %0, [%1];"
                             : "=l"(r) : "l"(&g_release));
            } while (r < target);
        }
        __threadfence();
    }
    __syncthreads();
}

__global__ __launch_bounds__(512, 1) void lstm_seq(
    const float* __restrict__ Wh,   // [512][2048]
    const float* __restrict__ bh,   // [2048]
    float* __restrict__ out)        // [2][64][512]
{
    extern __shared__ char smem[];
    u32 sb = smem_u32(smem);

    const int tid  = threadIdx.x;
    const int cta  = blockIdx.x;
    const int c0   = cta * 16;
    const int lane = tid & 31;
    const int wid  = tid >> 5;
    const int grp  = wid >> 3;          // k-half
    const int mw   = (wid >> 2) & 1;    // m 32-batch tile
    const int nh   = wid & 3;           // gate-col 16-tile

    // --- Stage Wh slice: rows n = q*4+g (q 0..15), k contiguous, fp16
    for (int idx = tid; idx < 64 * 512; idx += 512) {
        int n = idx & 63, k = idx >> 6;
        int q = n >> 2, g = n & 3;
        float v = Wh[(size_t)k * G4 + g * HDIM + c0 + q];
        *(__half*)(smem + SM_WST + n * APB + k * 2) = __float2half_rn(v);
    }
    __syncthreads();

    // --- B fragments into registers
    u32 bhi[16][4];
    {
        const u32 wrow = sb + SM_WST + (u32)(nh * 16 + (lane & 15)) * APB
                       + (u32)grp * 512 + (u32)(lane >> 4) * 16;
#pragma unroll
        for (int kk = 0; kk < 16; kk++) {
            LDSM4(bhi[kk][0], bhi[kk][1], bhi[kk][2], bhi[kk][3], wrow + kk * 32);
        }
    }

    // --- Per-lane identity: TWO states per thread (mt0, mt1)
    const int q   = nh * 4 + ((lane >> 1) & 1) + 2 * (lane & 1);
    const int col = c0 + q;
    const int b0  = mw * 32 + (lane >> 2) + grp * 8;   // mt0
    const int b1  = b0 + 16;                           // mt1

    float4 bhv;
    bhv.x = bh[0 * HDIM + col];
    bhv.y = bh[1 * HDIM + col];
    bhv.z = bh[2 * HDIM + col];
    bhv.w = bh[3 * HDIM + col];

    // Zero h buffer 0 (32768 halfs = 16384 u32; 32*512 = 16384 threads)
    ((u32*)g_hf[0])[cta * 512 + tid] = 0u;

    // Preload x_proj for t = 0
    float4 xc0, xc1;
    {
        const float* xb = g_xproj + (size_t)cta * 4096 + b0 * 64 + q * 4;
        xc0 = *(const float4*)xb;
        xc1 = *(const float4*)(xb + 1024);   // b1 = b0 + 16 -> +16*64
    }

    grid_barrier();

    float cst0 = 0.f, cst1 = 0.f;
    float hs0 = 0.f, hs1 = 0.f, cs0 = 0.f, cs1 = 0.f;

    const u32 arow0 = sb + SM_A + (u32)(mw * 32 + (lane & 15)) * APB
                    + (u32)grp * 512 + (u32)(lane >> 4) * 16;
    const u32 arow1 = arow0 + 16 * APB;
    const int rstart = mw * 32 + nh * 8;   // broadcast rows (8)
    const u32 sub = (u32)(wid & 7);
    const u32 red_mine  = SM_RED + (u32)grp * 8192 + sub * 1024 + (u32)lane * 16;
    const u32 red_other = SM_RED + (u32)(grp ^ 1) * 8192 + sub * 1024 + (u32)lane * 16;
    const int barid = 1 + grp * 2 + mw;

#pragma unroll 1
    for (int t = 0; t < T_STEPS; t++) {
        const int rb = t & 1;
        const __half* src = g_hf[rb];

        // --- Broadcast: this warp loads 8 rows x its k-half (4KB)
#pragma unroll
        for (int i = 0; i < 8; i++) {
            int row = rstart + i;
            u32 off = (u32)row * APB + (u32)grp * 512 + (u32)lane * 16;
            size_t go = (size_t)row * 1024 + grp * 512 + lane * 16;
            cpa16(sb + SM_A + off, (const char*)src + go);
        }
        CP_COMMIT();
        asm volatile("cp.async.wait_group 0;" ::: "memory");
        BAR_SYNC(barid, 128);   // 4 nh-warps of this (grp,mw) group

        // --- MMA: m32 x n16 x k-half (64 MMAs), B from registers
        float a0a[4] = {0.f, 0.f, 0.f, 0.f};
        float a0b[4] = {0.f, 0.f, 0.f, 0.f};
        float a1a[4] = {0.f, 0.f, 0.f, 0.f};
        float a1b[4] = {0.f, 0.f, 0.f, 0.f};
#pragma unroll
        for (int kk = 0; kk < 16; kk++) {
            u32 aA[4], aB[4];
            LDSM4(aA[0], aA[1], aA[2], aA[3], arow0 + kk * 32);
            LDSM4(aB[0], aB[1], aB[2], aB[3], arow1 + kk * 32);
            MMA_F16(a0a, aA, bhi[kk][0], bhi[kk][2]);
            MMA_F16(a0b, aA, bhi[kk][1], bhi[kk][3]);
            MMA_F16(a1a, aB, bhi[kk][0], bhi[kk][2]);
            MMA_F16(a1b, aB, bhi[kk][1], bhi[kk][3]);
        }

        // --- Cross-group split-K exchange (per m-tile)
        {
            float4 s0, s1;
            if (grp == 0) {
                s0.x = a0a[2]; s0.y = a0a[3]; s0.z = a0b[2]; s0.w = a0b[3];
                s1.x = a1a[2]; s1.y = a1a[3]; s1.z = a1b[2]; s1.w = a1b[3];
            } else {
                s0.x = a0a[0]; s0.y = a0a[1]; s0.z = a0b[0]; s0.w = a0b[1];
                s1.x = a1a[0]; s1.y = a1a[1]; s1.z = a1b[0]; s1.w = a1b[1];
            }
            *(float4*)(smem + red_mine)       = s0;
            *(float4*)(smem + red_mine + 512) = s1;
        }
        __syncthreads();

        float4 r0 = *(const float4*)(smem + red_other);
        float4 r1 = *(const float4*)(smem + red_other + 512);

        const bool odd = (lane & 1);
        float v0[2], v1[2], v2[2], v3[2];
        if (grp == 0) {
            v0[0] = a0a[0] + r0.x; v1[0] = a0a[1] + r0.y;
            v2[0] = a0b[0] + r0.z; v3[0] = a0b[1] + r0.w;
            v0[1] = a1a[0] + r1.x; v1[1] = a1a[1] + r1.y;
            v2[1] = a1b[0] + r1.z; v3[1] = a1b[1] + r1.w;
        } else {
            v0[0] = a0a[2] + r0.x; v1[0] = a0a[3] + r0.y;
            v2[0] = a0b[2] + r0.z; v3[0] = a0b[3] + r0.w;
            v0[1] = a1a[2] + r1.x; v1[1] = a1a[3] + r1.y;
            v2[1] = a1b[2] + r1.z; v3[1] = a1b[3] + r1.w;
        }

        const int nb = rb ^ 1;
#pragma unroll
        for (int mt = 0; mt < 2; mt++) {
            const float s0 = odd ? v0[mt] : v2[mt];
            const float s1 = odd ? v1[mt] : v3[mt];
            const float p0 = __shfl_xor_sync(0xffffffffu, s0, 1);
            const float p1 = __shfl_xor_sync(0xffffffffu, s1, 1);

            float gi, gf, go, gz;
            if (!odd) { gi = v0[mt]; gf = v1[mt]; go = p0; gz = p1; }
            else      { gi = p0;     gf = p1;     go = v2[mt]; gz = v3[mt]; }

            const float4 xc = mt ? xc1 : xc0;
            gi += xc.x + bhv.x; gf += xc.y + bhv.y;
            go += xc.z + bhv.z; gz += xc.w + bhv.w;

            const float iv = 1.f / (1.f + __expf(-gi));
            const float fv = 1.f / (1.f + __expf(-gf));
            const float ov = 1.f / (1.f + __expf(-go));
            const float zv = 1.f - 2.f / (__expf(2.f * gz) + 1.f);
            float& cst = mt ? cst1 : cst0;
            cst = fmaf(iv, zv, fv * cst);
            const float hv = ov * (1.f - 2.f / (__expf(2.f * cst) + 1.f));

            if (mt) { hs1 += hv; cs1 += cst; }
            else    { hs0 += hv; cs0 += cst; }

            const int bb = mt ? b1 : b0;
            g_hf[nb][bb * HDIM + col] = __float2half_rn(hv);
        }

        // Prefetch next step's x_proj (hides under barrier)
        if (t + 1 < T_STEPS) {
            const float* xb = g_xproj + (size_t)(t + 1) * 131072
                            + (size_t)cta * 4096 + b0 * 64 + q * 4;
            xc0 = *(const float4*)xb;
            xc1 = *(const float4*)(xb + 1024);
        }

        grid_barrier();
    }

    const float inv = 1.0f / (float)T_STEPS;
    out[b0 * HDIM + col]                = hs0 * inv;
    out[BATCH * HDIM + b0 * HDIM + col] = cs0 * inv;
    out[b1 * HDIM + col]                = hs1 * inv;
    out[BATCH * HDIM + b1 * HDIM + col] = cs1 * inv;
}

// ---------------------------------------------------------------------------
extern "C" void kernel_launch(void* const* d_in, const int* in_sizes, int n_in,
                              void* d_out, int out_size) {
    const float* X  = (const float*)d_in[0];
    const float* Wx = (const float*)d_in[1];
    const float* bx = (const float*)d_in[2];
    const float* Wh = (const float*)d_in[3];
    const float* bh = (const float*)d_in[4];
    float* out = (float*)d_out;

    cudaFuncSetAttribute(gemm_xproj_hmma,
                         cudaFuncAttributeMaxDynamicSharedMemorySize, GSM_TOTAL);
    cudaFuncSetAttribute(lstm_seq,
                         cudaFuncAttributeMaxDynamicSharedMemorySize, SM_TOTAL);

    convert_x<<<65536, 256>>>(X);
    convert_w<<<4096, 256>>>(Wx);

    dim3 gemm_grid(16, 1024);
    gemm_xproj_hmma<<<gemm_grid, 256, GSM_TOTAL>>>(bx);

    lstm_seq<<<NBLK, 512, SM_TOTAL>>>(Wh, bh, out);
}

// round 17
// speedup vs baseline: 1.2798x; 1.2798x over previous
#include <cuda_runtime.h>
#include <cuda_fp16.h>
#include <math.h>

// Problem dims
#define T_STEPS 2048
#define BATCH   64
#define DIN     512
#define HDIM    512
#define G4      2048            // 4*H
#define M_ROWS  131072          // T*B
#define NBLK    128

typedef unsigned long long u64;
typedef unsigned int u32;

// Scratch (device globals: allocation-free contract)
// g_xproj layout: [t][cta(128)][batch(64)][q(4)][g(4)] fp32
__device__ float g_xproj[268435456];            // 1 GiB
__device__ __half g_xh[67108864];               // X fp16 (single plane)
__device__ __half g_wxt[1048576];               // Wx^T fp16, row r = hc*4+g
__device__ __half g_hf[2][32768];               // h state fp16 [buf][b*512+col]
__device__ unsigned long long g_arrive  = 0ULL;
__device__ unsigned long long g_release = 0ULL;

// ---------------------------------------------------------------------------
// PTX helpers
// ---------------------------------------------------------------------------
__device__ __forceinline__ u32 smem_u32(const void* p) {
    u32 a;
    asm("{ .reg .u64 t; cvta.to.shared.u64 t, %1; cvt.u32.u64 %0, t; }"
        : "=r"(a) : "l"(p));
    return a;
}
__device__ __forceinline__ void cpa16(u32 dst, const void* src) {
    asm volatile("cp.async.cg.shared.global [%0], [%1], 16;"
                 :: "r"(dst), "l"(src));
}
#define CP_COMMIT() asm volatile("cp.async.commit_group;" ::: "memory")

#define LDSM4(r0, r1, r2, r3, a) \
    asm volatile("ldmatrix.sync.aligned.m8n8.x4.shared.b16 {%0,%1,%2,%3}, [%4];" \
                 : "=r"(r0), "=r"(r1), "=r"(r2), "=r"(r3) : "r"(a))

#define MMA_F16B(c, a, b) \
    asm volatile("mma.sync.aligned.m16n8k16.row.col.f32.f16.f16.f32 " \
                 "{%0,%1,%2,%3}, {%4,%5,%6,%7}, {%8,%9}, {%0,%1,%2,%3};" \
                 : "+f"((c)[0]), "+f"((c)[1]), "+f"((c)[2]), "+f"((c)[3]) \
                 : "r"((a)[0]), "r"((a)[1]), "r"((a)[2]), "r"((a)[3]), \
                   "r"((b)[0]), "r"((b)[1]))

#define MMA_F16(c, a, b0r, b1r) \
    asm volatile("mma.sync.aligned.m16n8k16.row.col.f32.f16.f16.f32 " \
                 "{%0,%1,%2,%3}, {%4,%5,%6,%7}, {%8,%9}, {%0,%1,%2,%3};" \
                 : "+f"((c)[0]), "+f"((c)[1]), "+f"((c)[2]), "+f"((c)[3]) \
                 : "r"((a)[0]), "r"((a)[1]), "r"((a)[2]), "r"((a)[3]), \
                   "r"(b0r), "r"(b1r))

// ---------------------------------------------------------------------------
// Conversion kernels: fp32 -> fp16 (single plane)
// ---------------------------------------------------------------------------
__global__ __launch_bounds__(256) void convert_x(const float* __restrict__ X) {
    size_t i = (size_t)blockIdx.x * 256 + threadIdx.x;   // 16777216 float4
    float4 v = ((const float4*)X)[i];
    __half2* ph = (__half2*)g_xh;
    ph[i * 2]     = __floats2half2_rn(v.x, v.y);
    ph[i * 2 + 1] = __floats2half2_rn(v.z, v.w);
}

// Wx [k 512][col 2048] -> g_wxt row r = (col&511)*4 + (col>>9), K-contiguous
__global__ __launch_bounds__(256) void convert_w(const float* __restrict__ Wx) {
    int idx = blockIdx.x * 256 + threadIdx.x;    // 1048576
    int k = idx >> 11, col = idx & 2047;
    int r = (col & 511) * 4 + (col >> 9);
    g_wxt[(size_t)r * 512 + k] = __float2half_rn(Wx[idx]);
}

// ---------------------------------------------------------------------------
// Kernel 1: x_proj = X @ Wx + bx via mma.sync fp16 single-plane (K=512).
// N-tile = 128 permuted B rows = 32 h-cols x 4 gates => epilogue writes are
// float2-coalesced (lanes 0-3 fill 32B contiguous; zero write amplification).
// 3-stage cp.async pipeline, one __syncthreads per 32-K chunk.
// ---------------------------------------------------------------------------
#define TILE_B   10240          // 128 rows * 80 bytes
#define GSTAGE   20480          // A tile + B tile per stage
#define GSM_TOTAL (3 * GSTAGE)  // 61440

__device__ __forceinline__ void load_tile(
    u32 sA, u32 sB,
    const __half* __restrict__ asrc,
    const __half* __restrict__ bsrc,
    int kc, int tid)
{
#pragma unroll
    for (int p = 0; p < 2; p++) {
        int idx = tid + p * 256;
        int row = idx >> 2, seg = idx & 3;
        cpa16(sA + row * 80 + seg * 16,
              (const char*)(asrc + (size_t)row * 512 + kc) + seg * 16);
    }
#pragma unroll
    for (int p = 0; p < 2; p++) {
        int idx = tid + p * 256;
        int row = idx >> 2, seg = idx & 3;
        cpa16(sB + row * 80 + seg * 16,
              (const char*)(bsrc + (size_t)row * 512 + kc) + seg * 16);
    }
}

__global__ __launch_bounds__(256, 2) void gemm_xproj_hmma(
    const float* __restrict__ bias)
{
    extern __shared__ char gsm[];
    u32 sb = smem_u32(gsm);

    const int tid  = threadIdx.x;
    const int lane = tid & 31;
    const int wid  = tid >> 5;
    const int m0w  = (wid & 3) * 32;
    const int n0w  = (wid >> 2) * 64;

    const int bn  = blockIdx.x * 128;   // B row block (permuted rows)
    const int hb  = blockIdx.x * 32;    // h-col block
    const int m0  = blockIdx.y * 128;

    const __half* a_src = g_xh + (size_t)m0 * 512;
    const __half* b_src = g_wxt + (size_t)bn * 512;

    float acc[2][8][4];
#pragma unroll
    for (int mt = 0; mt < 2; mt++)
#pragma unroll
        for (int nt = 0; nt < 8; nt++)
#pragma unroll
            for (int r = 0; r < 4; r++) acc[mt][nt][r] = 0.f;

    // Prologue: chunks 0 and 1 into stages 0 and 1
    load_tile(sb,          sb + TILE_B,          a_src, b_src, 0,  tid);
    CP_COMMIT();
    load_tile(sb + GSTAGE, sb + GSTAGE + TILE_B, a_src, b_src, 32, tid);
    CP_COMMIT();

    int st = 0, pst = 2;
#pragma unroll 1
    for (int c = 0; c < 16; c++) {
        if (c < 15) {
            asm volatile("cp.async.wait_group 1;" ::: "memory");
        } else {
            asm volatile("cp.async.wait_group 0;" ::: "memory");
        }
        __syncthreads();

        if (c + 2 < 16) {
            const int kc = (c + 2) * 32;
            u32 base = sb + (u32)pst * GSTAGE;
            load_tile(base, base + TILE_B, a_src, b_src, kc, tid);
            CP_COMMIT();
        }

        const u32 sA = sb + (u32)st * GSTAGE;
        const u32 sB = sA + TILE_B;

#pragma unroll
        for (int k16 = 0; k16 < 2; k16++) {
            const int kb = k16 * 16;
            u32 a_frag[2][4];
#pragma unroll
            for (int mt = 0; mt < 2; mt++) {
                u32 addr = sA + (u32)((m0w + mt * 16 + (lane & 15)) * 40
                                      + kb + (lane >> 4) * 8) * 2;
                LDSM4(a_frag[mt][0], a_frag[mt][1], a_frag[mt][2], a_frag[mt][3], addr);
            }
            u32 b_frag[8][2];
#pragma unroll
            for (int ntp = 0; ntp < 4; ntp++) {
                u32 addr = sB + (u32)((n0w + ntp * 16 + (lane & 15)) * 40
                                      + kb + (lane >> 4) * 8) * 2;
                u32 r0, r1, r2, r3;
                LDSM4(r0, r1, r2, r3, addr);
                b_frag[2 * ntp][0]     = r0;
                b_frag[2 * ntp][1]     = r2;
                b_frag[2 * ntp + 1][0] = r1;
                b_frag[2 * ntp + 1][1] = r3;
            }
#pragma unroll
            for (int mt = 0; mt < 2; mt++)
#pragma unroll
                for (int nt = 0; nt < 8; nt++)
                    MMA_F16B(acc[mt][nt], a_frag[mt], b_frag[nt]);
        }

        st = (st == 2) ? 0 : st + 1;
        pst = (pst == 2) ? 0 : pst + 1;
    }

    // Epilogue: bias + coalesced float2 stores into [t][cta][b][q][g]
    // Thread cols j = n0w + (lane&3)*2 + nt*8 (tile rows, permuted): even j
    // => (g, g+1) of h-col hc = hb + (j>>2).
    float bx0[8], bx1[8];
#pragma unroll
    for (int nt = 0; nt < 8; nt++) {
        const int j  = n0w + (lane & 3) * 2 + nt * 8;
        const int hc = hb + (j >> 2);
        const int g  = j & 3;
        bx0[nt] = __ldg(&bias[g * 512 + hc]);
        bx1[nt] = __ldg(&bias[(g + 1) * 512 + hc]);
    }
#pragma unroll
    for (int mt = 0; mt < 2; mt++) {
#pragma unroll
        for (int nt = 0; nt < 8; nt++) {
            const int j  = n0w + (lane & 3) * 2 + nt * 8;
            const int hc = hb + (j >> 2);
            const int g  = j & 3;
            const size_t coff = (size_t)(hc >> 2) * 1024 + (hc & 3) * 4 + g;
            const int rA = m0 + m0w + (lane >> 2) + mt * 16;
            const int rB = rA + 8;
            const size_t iA = (size_t)(rA >> 6) * 131072 + (rA & 63) * 16 + coff;
            const size_t iB = (size_t)(rB >> 6) * 131072 + (rB & 63) * 16 + coff;
            float2 vA, vB;
            vA.x = acc[mt][nt][0] + bx0[nt]; vA.y = acc[mt][nt][1] + bx1[nt];
            vB.x = acc[mt][nt][2] + bx0[nt]; vB.y = acc[mt][nt][3] + bx1[nt];
            *(float2*)(g_xproj + iA) = vA;
            *(float2*)(g_xproj + iB) = vB;
        }
    }
}

// ---------------------------------------------------------------------------
// Kernel 2: persistent recurrence — R15 VERBATIM (measured best).
// h fp16 single-plane; Wh fp16 single-plane in registers; centralized atomic
// barrier; warp-local pipelined broadcast; gates split across warp groups.
// ---------------------------------------------------------------------------
#define APB 1040          // plane row pitch bytes (512 fp16 + 8 pad)
#define SM_A    0         // 64*1040 = 66560
#define SM_RED  66560     // 4096
#define SM_WST  70656     // W hi plane: 16*1040 = 16640
#define SM_TOTAL 87296

__device__ __forceinline__ void grid_barrier() {
    __syncthreads();
    if (threadIdx.x == 0) {
        __threadfence();
        unsigned long long t = atomicAdd(&g_arrive, 1ULL) + 1ULL;
        unsigned long long n = (unsigned long long)NBLK;
        unsigned long long target = ((t + n - 1ULL) / n) * n;
        if (t == target) {
            atomicMax(&g_release, target);
        } else {
            unsigned long long r;
            do {
                asm volatile("ld.volatile.global.u64 %0, [%1];"
                             : "=l"(r) : "l"(&g_release));
            } while (r < target);
        }
        __threadfence();
    }
    __syncthreads();
}

__global__ __launch_bounds__(256, 1) void lstm_seq(
    const float* __restrict__ Wh,   // [512][2048]
    const float* __restrict__ bh,   // [2048]
    float* __restrict__ out)        // [2][64][512]
{
    extern __shared__ char smem[];
    u32 sb = smem_u32(smem);

    const int tid  = threadIdx.x;
    const int cta  = blockIdx.x;
    const int c0   = cta * 4;
    const int lane = tid & 31;
    const int wid  = tid >> 5;
    const int grp  = wid >> 2;     // k-half: 0 -> k[0:256), 1 -> k[256:512)
    const int mw   = wid & 3;      // m-tile (16 batches)

    // --- Stage Wh slice into smem fp16 (single plane), rows n = q*4+g
    for (int idx = tid; idx < 16 * 512; idx += 256) {
        int n = idx & 15, k = idx >> 4;
        int q = n >> 2, g = n & 3;
        float v = Wh[(size_t)k * G4 + g * HDIM + c0 + q];
        *(__half*)(smem + SM_WST + n * APB + k * 2) = __float2half_rn(v);
    }
    __syncthreads();

    // --- B fragments into registers (held for the whole run)
    u32 bhi[16][4];
    {
        const u32 wrow_h = sb + SM_WST + (u32)(lane & 15) * APB
                         + (u32)grp * 512 + (u32)(lane >> 4) * 16;
#pragma unroll
        for (int kk = 0; kk < 16; kk++) {
            LDSM4(bhi[kk][0], bhi[kk][1], bhi[kk][2], bhi[kk][3], wrow_h + kk * 32);
        }
    }

    // --- Per-lane state identity: ONE state per thread.
    const int q    = ((lane >> 1) & 1) + 2 * (lane & 1);
    const int col  = c0 + q;
    const int bsel = mw * 16 + (lane >> 2) + grp * 8;

    float4 bhv;
    bhv.x = bh[0 * HDIM + col];
    bhv.y = bh[1 * HDIM + col];
    bhv.z = bh[2 * HDIM + col];
    bhv.w = bh[3 * HDIM + col];

    // Zero h buffer 0 (32768 halfs = 16384 u32)
    {
        int gt = cta * 256 + tid;
        if (gt < 16384) ((u32*)g_hf[0])[gt] = 0u;
    }

    // Preload x_proj for t = 0 (hidden under the initial barrier)
    float4 xc;
    {
        const float* xb = g_xproj + (size_t)cta * 1024 + bsel * 16 + q * 4;
        xc = *(const float4*)xb;
    }

    grid_barrier();

    float cst = 0.f, hsum = 0.f, csum = 0.f;

    const u32 arow = sb + SM_A + (u32)(mw * 16 + (lane & 15)) * APB
                   + (u32)grp * 512 + (u32)(lane >> 4) * 16;
    const int brow = mw * 16 + (lane >> 4);
    const u32 bseg = (u32)grp * 512 + (u32)(lane & 15) * 16;
    const u32 red_mine  = SM_RED + (u32)grp * 2048 + (u32)mw * 512 + (u32)lane * 16;
    const u32 red_other = SM_RED + (u32)(grp ^ 1) * 2048 + (u32)mw * 512 + (u32)lane * 16;

#pragma unroll 1
    for (int t = 0; t < T_STEPS; t++) {
        const int rb = t & 1;
        const __half* src = g_hf[rb];

        // --- Warp-local h broadcast: 2 pipelined 4KB k-chunks
#pragma unroll
        for (int c2 = 0; c2 < 2; c2++) {
#pragma unroll
            for (int j = 0; j < 8; j++) {
                int row = brow + j * 2;
                u32 off = (u32)row * APB + (u32)c2 * 256 + bseg;
                size_t go = (size_t)row * 1024 + c2 * 256 + (bseg & 1023);
                cpa16(sb + SM_A + off, (const char*)src + go);
            }
            CP_COMMIT();
        }

        // --- MMA m16n16, pipelined across the two chunks; B from registers
        float acc0[4] = {0.f, 0.f, 0.f, 0.f};
        float acc1[4] = {0.f, 0.f, 0.f, 0.f};

        asm volatile("cp.async.wait_group 1;" ::: "memory");
        __syncwarp(0xffffffffu);
#pragma unroll
        for (int kk = 0; kk < 8; kk++) {
            u32 a[4];
            LDSM4(a[0], a[1], a[2], a[3], arow + kk * 32);
            MMA_F16(acc0, a, bhi[kk][0], bhi[kk][2]);
            MMA_F16(acc1, a, bhi[kk][1], bhi[kk][3]);
        }
        asm volatile("cp.async.wait_group 0;" ::: "memory");
        __syncwarp(0xffffffffu);
#pragma unroll
        for (int kk = 8; kk < 16; kk++) {
            u32 a[4];
            LDSM4(a[0], a[1], a[2], a[3], arow + kk * 32);
            MMA_F16(acc0, a, bhi[kk][0], bhi[kk][2]);
            MMA_F16(acc1, a, bhi[kk][1], bhi[kk][3]);
        }

        // --- Cross-group split-K exchange
        {
            float4 ship;
            if (grp == 0) {
                ship.x = acc0[2]; ship.y = acc0[3];
                ship.z = acc1[2]; ship.w = acc1[3];
            } else {
                ship.x = acc0[0]; ship.y = acc0[1];
                ship.z = acc1[0]; ship.w = acc1[1];
            }
            *(float4*)(smem + red_mine) = ship;
        }
        __syncthreads();

        float v0, v1, v2, v3;
        {
            float4 r = *(const float4*)(smem + red_other);
            if (grp == 0) {
                v0 = acc0[0] + r.x; v1 = acc0[1] + r.y;
                v2 = acc1[0] + r.z; v3 = acc1[1] + r.w;
            } else {
                v0 = acc0[2] + r.x; v1 = acc0[3] + r.y;
                v2 = acc1[2] + r.z; v3 = acc1[3] + r.w;
            }
        }

        // --- Pair exchange within lane pairs: gather the 4 gates
        const bool odd = (lane & 1);
        const float s0 = odd ? v0 : v2;
        const float s1 = odd ? v1 : v3;
        const float r0 = __shfl_xor_sync(0xffffffffu, s0, 1);
        const float r1 = __shfl_xor_sync(0xffffffffu, s1, 1);

        float gi, gf, go, gz;
        if (!odd) { gi = v0; gf = v1; go = r0; gz = r1; }
        else      { gi = r0; gf = r1; go = v2; gz = v3; }

        gi += xc.x + bhv.x; gf += xc.y + bhv.y;
        go += xc.z + bhv.z; gz += xc.w + bhv.w;

        const float iv = 1.f / (1.f + __expf(-gi));
        const float fv = 1.f / (1.f + __expf(-gf));
        const float ov = 1.f / (1.f + __expf(-go));
        const float zv = 1.f - 2.f / (__expf(2.f * gz) + 1.f);
        cst = fmaf(iv, zv, fv * cst);
        const float hv = ov * (1.f - 2.f / (__expf(2.f * cst) + 1.f));

        hsum += hv; csum += cst;

        g_hf[rb ^ 1][bsel * HDIM + col] = __float2half_rn(hv);

        // Prefetch next step's x_proj (hides under barrier)
        if (t + 1 < T_STEPS) {
            const float* xb = g_xproj + (size_t)(t + 1) * 131072
                            + (size_t)cta * 1024 + bsel * 16 + q * 4;
            xc = *(const float4*)xb;
        }

        grid_barrier();
    }

    const float inv = 1.0f / (float)T_STEPS;
    out[bsel * HDIM + col]                = hsum * inv;
    out[BATCH * HDIM + bsel * HDIM + col] = csum * inv;
}

// ---------------------------------------------------------------------------
extern "C" void kernel_launch(void* const* d_in, const int* in_sizes, int n_in,
                              void* d_out, int out_size) {
    const float* X  = (const float*)d_in[0];
    const float* Wx = (const float*)d_in[1];
    const float* bx = (const float*)d_in[2];
    const float* Wh = (const float*)d_in[3];
    const float* bh = (const float*)d_in[4];
    float* out = (float*)d_out;

    cudaFuncSetAttribute(gemm_xproj_hmma,
                         cudaFuncAttributeMaxDynamicSharedMemorySize, GSM_TOTAL);
    cudaFuncSetAttribute(lstm_seq,
                         cudaFuncAttributeMaxDynamicSharedMemorySize, SM_TOTAL);

    convert_x<<<65536, 256>>>(X);
    convert_w<<<4096, 256>>>(Wx);

    dim3 gemm_grid(16, 1024);
    gemm_xproj_hmma<<<gemm_grid, 256, GSM_TOTAL>>>(bx);

    lstm_seq<<<NBLK, 256, SM_TOTAL>>>(Wh, bh, out);
}